// round 7
// baseline (speedup 1.0000x reference)
#include <cuda_runtime.h>
#include <cstdint>
#include <cstddef>

#define B_ 8
#define N_ 4096
#define M_ 4096
#define C_ 256

#define SPLITS 8
#define KM_PER_SPLIT 16      // 16 * 32 = 512 m-rows per split
#define STA 136              // stride (words) for kv's raw-v [32][128] tile

// Scratch (static device arrays; no allocations allowed)
__device__ float    g_rq[B_ * N_];                 // 1/(N*max(||q||,eps))
__device__ float    g_rk[B_ * M_];                 // 1/max(||k||,eps)
__device__ float    g_kvp[SPLITS * B_ * C_ * C_];  // split-K partials [sp][b][c][d]
__device__ uint32_t g_kv[B_ * C_ * C_];            // reduced kv, B-frag packed tf32

__device__ __forceinline__ uint32_t f2tf(float x) {
    uint32_t r;
    asm("cvt.rna.tf32.f32 %0, %1;" : "=r"(r) : "f"(x));
    return r;
}

__device__ __forceinline__ void mma8(float c[4], const uint32_t a[4], const uint32_t b[2]) {
    asm volatile(
        "mma.sync.aligned.m16n8k8.row.col.f32.tf32.tf32.f32 "
        "{%0,%1,%2,%3}, {%4,%5,%6,%7}, {%8,%9}, {%0,%1,%2,%3};\n"
        : "+f"(c[0]), "+f"(c[1]), "+f"(c[2]), "+f"(c[3])
        : "r"(a[0]), "r"(a[1]), "r"(a[2]), "r"(a[3]),
          "r"(b[0]), "r"(b[1]));
}

__device__ __forceinline__ void cp16(void* smem, const void* gmem) {
    uint32_t s = (uint32_t)__cvta_generic_to_shared(smem);
    asm volatile("cp.async.cg.shared.global [%0], [%1], 16;\n" :: "r"(s), "l"(gmem));
}
__device__ __forceinline__ void cp_commit() { asm volatile("cp.async.commit_group;\n" ::: "memory"); }
template <int NN>
__device__ __forceinline__ void cp_wait() { asm volatile("cp.async.wait_group %0;\n" :: "n"(NN) : "memory"); }

// ---------------------------------------------------------------------------
// Kernel 1: reciprocal L2 norms only (tiny outputs; no data copies).
// ---------------------------------------------------------------------------
__global__ __launch_bounds__(256) void rnorm_kernel(const float* __restrict__ q,
                                                    const float* __restrict__ k) {
    const int gw = (blockIdx.x * blockDim.x + threadIdx.x) >> 5;
    const int lane = threadIdx.x & 31;
    const bool is_q = (gw < B_ * N_);
    const int r = is_q ? gw : gw - B_ * N_;
    const float* src = (is_q ? q : k) + (size_t)r * C_;

    float4 a = *(const float4*)(src + lane * 4);
    float4 b = *(const float4*)(src + 128 + lane * 4);
    float ss = a.x * a.x + a.y * a.y + a.z * a.z + a.w * a.w
             + b.x * b.x + b.y * b.y + b.z * b.z + b.w * b.w;
#pragma unroll
    for (int o = 16; o > 0; o >>= 1) ss += __shfl_xor_sync(0xffffffffu, ss, o);
    if (lane == 0) {
        float rn = (ss > 1e-24f) ? rsqrtf(ss) : 1e12f;
        if (is_q) g_rq[r] = rn * (1.0f / (float)N_);
        else      g_rk[r] = rn;
    }
}

// ---------------------------------------------------------------------------
// Kernel 2: split-K partials of kv[b][c][d] = sum_m (k[m][c]*rk[m]) * v[m][d]
// CTA 128(c) x 128(d), BK=32 (m), 2 CTAs/SM.
// A: raw k gathered LDG -> regs -> (scale, cvt) -> packed-frag STS.128,
//    register double-buffered one full stage ahead.
// B: raw v via cp.async, cvt in inner loop (validated R4 form).
// ---------------------------------------------------------------------------
__global__ __launch_bounds__(256, 2) void kv_kernel(const float* __restrict__ k,
                                                    const float* __restrict__ v) {
    extern __shared__ uint32_t sm[];
    uint32_t* As = sm;                        // [2][4096] packed A
    float*    Bs = (float*)(sm + 2 * 4096);   // [2][32*STA] raw fp32

    const int bz = blockIdx.z;       // b*8 + split
    const int b  = bz >> 3;
    const int sp = bz & 7;
    const int c0 = blockIdx.y * 128;
    const int d0 = blockIdx.x * 128;
    const int m_base = sp * (KM_PER_SPLIT * 32);

    const int t = threadIdx.x, lane = t & 31, wid = t >> 5;
    const int g = lane >> 2, tig = lane & 3;
    const int wc = (wid >> 2) * 64;
    const int wd = (wid & 3) * 32;
    const int lr = t >> 3;
    const int lq = (t & 7) * 4;

    const float* kb  = k + (size_t)b * M_ * C_;
    const float* vb  = v + (size_t)b * M_ * C_ + d0;
    const float* rkb = g_rk + b * M_;

    // this thread's 4 A blocks: bid = wid*4+i -> (kk = bid>>3, c16t = bid&7)
    int kkA[4], ctA[4];
#pragma unroll
    for (int i = 0; i < 4; i++) { const int bid = wid * 4 + i; kkA[i] = bid >> 3; ctA[i] = bid & 7; }

    float pv[4][4];
    float pr[4][2];

#define KV_LOAD_A(m0) do { \
    _Pragma("unroll") \
    for (int i = 0; i < 4; i++) { \
        const int mr = (m0) + kkA[i] * 8 + tig; \
        const int cc = c0 + ctA[i] * 16 + g; \
        pv[i][0] = kb[(size_t)mr * C_ + cc]; \
        pv[i][1] = kb[(size_t)mr * C_ + cc + 8]; \
        pv[i][2] = kb[(size_t)(mr + 4) * C_ + cc]; \
        pv[i][3] = kb[(size_t)(mr + 4) * C_ + cc + 8]; \
        pr[i][0] = __ldg(rkb + mr); \
        pr[i][1] = __ldg(rkb + mr + 4); \
    } \
} while (0)

#define KV_STS_A(dst) do { \
    _Pragma("unroll") \
    for (int i = 0; i < 4; i++) { \
        uint4 o; \
        o.x = f2tf(pv[i][0] * pr[i][0]); \
        o.y = f2tf(pv[i][1] * pr[i][0]); \
        o.z = f2tf(pv[i][2] * pr[i][1]); \
        o.w = f2tf(pv[i][3] * pr[i][1]); \
        *(uint4*)&(dst)[(kkA[i] * 8 + ctA[i]) * 128 + lane * 4] = o; \
    } \
} while (0)

    // prologue: stage 0 A (regs -> SMEM), stage 0 B (cp.async), prefetch stage 1 A
    KV_LOAD_A(m_base);
    KV_STS_A(As);
#pragma unroll
    for (int i = 0; i < 4; i++)
        cp16(&Bs[lr * STA + lq + i * 32], vb + (size_t)(m_base + lr) * C_ + lq + i * 32);
    cp_commit();
    KV_LOAD_A(m_base + 32);

    float acc[4][4][4] = {};

#pragma unroll 1
    for (int km = 0; km < KM_PER_SPLIT; km++) {
        const int cur = km & 1;
        const int nxt = cur ^ 1;
        if (km + 1 < KM_PER_SPLIT) {
            const int m0 = m_base + (km + 1) * 32;
            float* Bn = &Bs[nxt * 32 * STA];
#pragma unroll
            for (int i = 0; i < 4; i++)
                cp16(&Bn[lr * STA + lq + i * 32], vb + (size_t)(m0 + lr) * C_ + lq + i * 32);
            cp_commit();
            cp_wait<1>();
        } else {
            cp_wait<0>();
        }
        __syncthreads();

        const uint32_t* Ac = &As[cur * 4096];
        const float*    Bc = &Bs[cur * 32 * STA];
#pragma unroll
        for (int kk = 0; kk < 4; kk++) {
            const int k8 = kk * 8;
            uint32_t af[4][4];
            uint32_t bf[4][2];
#pragma unroll
            for (int mt = 0; mt < 4; mt++) {
                const int rt = (wid >> 2) * 4 + mt;
                const uint4 pk = *(const uint4*)&Ac[(kk * 8 + rt) * 128 + lane * 4];
                af[mt][0] = pk.x; af[mt][1] = pk.y; af[mt][2] = pk.z; af[mt][3] = pk.w;
            }
#pragma unroll
            for (int nt = 0; nt < 4; nt++) {
                const int col = wd + nt * 8 + g;
                bf[nt][0] = f2tf(Bc[(k8 + tig) * STA + col]);
                bf[nt][1] = f2tf(Bc[(k8 + tig + 4) * STA + col]);
            }
#pragma unroll
            for (int mt = 0; mt < 4; mt++)
#pragma unroll
                for (int nt = 0; nt < 4; nt++)
                    mma8(acc[mt][nt], af[mt], bf[nt]);
        }

        if (km + 1 < KM_PER_SPLIT) {
            KV_STS_A(&As[nxt * 4096]);
            if (km + 2 < KM_PER_SPLIT) KV_LOAD_A(m_base + (km + 2) * 32);
        }
        __syncthreads();
    }

    float* kvp = g_kvp + ((size_t)sp * B_ + b) * C_ * C_;
#pragma unroll
    for (int mt = 0; mt < 4; mt++)
#pragma unroll
        for (int nt = 0; nt < 4; nt++) {
            const int c = c0 + wc + mt * 16 + g;
            const int d = d0 + wd + nt * 8 + tig * 2;
            float2 v0 = make_float2(acc[mt][nt][0], acc[mt][nt][1]);
            float2 v1 = make_float2(acc[mt][nt][2], acc[mt][nt][3]);
            *(float2*)&kvp[(size_t)c * C_ + d]       = v0;
            *(float2*)&kvp[(size_t)(c + 8) * C_ + d] = v1;
        }
}

// ---------------------------------------------------------------------------
// Kernel 2b: reduce partials -> packed tf32 B-frags (validated R4 form).
// ---------------------------------------------------------------------------
__global__ __launch_bounds__(256) void reduce_kernel() {
    const int idx = blockIdx.x * blockDim.x + threadIdx.x;
    const int lane = idx & 31;
    const int d8t  = (idx >> 5) & 15;
    const int kk   = (idx >> 9) & 3;
    const int km   = (idx >> 11) & 7;
    const int dt   = (idx >> 14) & 1;
    const int b    = idx >> 15;
    const int g = lane >> 2, tig = lane & 3;
    const int c = km * 32 + kk * 8 + tig;
    const int d = dt * 128 + d8t * 8 + g;

    float s0 = 0.0f, s1 = 0.0f;
#pragma unroll
    for (int sp = 0; sp < SPLITS; sp++) {
        const float* base = g_kvp + ((size_t)(sp * B_ + b) << 16);
        s0 += base[(size_t)c * C_ + d];
        s1 += base[(size_t)(c + 4) * C_ + d];
    }
    uint2 o;
    o.x = f2tf(s0);
    o.y = f2tf(s1);
    *(uint2*)&g_kv[(size_t)idx * 2] = o;
}

// ---------------------------------------------------------------------------
// Kernel 3: out[b][n][d] = rq[n] * sum_c q[n][c] * kv[c][d]
// CTA 128(n) x 128(d), BK=32 (c), 2 CTAs/SM.
// A: raw q gathered LDG -> cvt -> packed-frag STS (double-buffered regs).
// B: packed kv via cp.async. rq applied at epilogue.
// ---------------------------------------------------------------------------
__global__ __launch_bounds__(256, 2) void ctx_kernel(const float* __restrict__ q,
                                                     float* __restrict__ out) {
    extern __shared__ uint32_t sm[];
    uint32_t* As = sm;              // [2][4096]
    uint32_t* Bs = sm + 2 * 4096;   // [2][4096]

    const int b  = blockIdx.z;
    const int n_tile = blockIdx.y;
    const int dt = blockIdx.x;
    const int n0 = n_tile * 128;
    const int d0 = dt * 128;

    const int t = threadIdx.x, lane = t & 31, wid = t >> 5;
    const int g = lane >> 2, tig = lane & 3;
    const int wn = (wid >> 2) * 64;
    const int wd = (wid & 3) * 32;

    const float*    qb  = q + ((size_t)b * N_ + n0) * C_;
    const uint32_t* kvb = g_kv + (size_t)(b * 2 + dt) * 32768;

    // this thread's 4 A blocks: bid = wid*4+i -> (kk = bid>>3, rt = bid&7)
    int kkA[4], rtA[4];
#pragma unroll
    for (int i = 0; i < 4; i++) { const int bid = wid * 4 + i; kkA[i] = bid >> 3; rtA[i] = bid & 7; }

    float pv[4][4];

#define CTX_LOAD_A(cb) do { \
    _Pragma("unroll") \
    for (int i = 0; i < 4; i++) { \
        const int nr = rtA[i] * 16 + g; \
        const int cc = (cb) + kkA[i] * 8 + tig; \
        pv[i][0] = qb[(size_t)nr * C_ + cc]; \
        pv[i][1] = qb[(size_t)(nr + 8) * C_ + cc]; \
        pv[i][2] = qb[(size_t)nr * C_ + cc + 4]; \
        pv[i][3] = qb[(size_t)(nr + 8) * C_ + cc + 4]; \
    } \
} while (0)

#define CTX_STS_A(dst) do { \
    _Pragma("unroll") \
    for (int i = 0; i < 4; i++) { \
        uint4 o; \
        o.x = f2tf(pv[i][0]); \
        o.y = f2tf(pv[i][1]); \
        o.z = f2tf(pv[i][2]); \
        o.w = f2tf(pv[i][3]); \
        *(uint4*)&(dst)[(kkA[i] * 8 + rtA[i]) * 128 + lane * 4] = o; \
    } \
} while (0)

    // epilogue scales
    float rq0[4], rq1[4];
#pragma unroll
    for (int mt = 0; mt < 4; mt++) {
        const int n = n0 + wn + mt * 16 + g;
        rq0[mt] = __ldg(&g_rq[b * N_ + n]);
        rq1[mt] = __ldg(&g_rq[b * N_ + n + 8]);
    }

    // prologue
    CTX_LOAD_A(0);
    CTX_STS_A(As);
#pragma unroll
    for (int i = 0; i < 4; i++)
        cp16(&Bs[t * 4 + i * 1024], kvb + t * 4 + i * 1024);
    cp_commit();
    CTX_LOAD_A(32);

    float acc[4][4][4] = {};
    const int KM = C_ / 32;   // 8

#pragma unroll 1
    for (int km = 0; km < KM; km++) {
        const int cur = km & 1;
        const int nxt = cur ^ 1;
        if (km + 1 < KM) {
            const uint32_t* sB = kvb + (size_t)(km + 1) * 4096;
            uint32_t* Bn = &Bs[nxt * 4096];
#pragma unroll
            for (int i = 0; i < 4; i++)
                cp16(&Bn[t * 4 + i * 1024], sB + t * 4 + i * 1024);
            cp_commit();
            cp_wait<1>();
        } else {
            cp_wait<0>();
        }
        __syncthreads();

        const uint32_t* Ac = &As[cur * 4096];
        const uint32_t* Bc = &Bs[cur * 4096];
#pragma unroll
        for (int kk = 0; kk < 4; kk++) {
            uint32_t af[4][4];
            uint32_t bf[4][2];
#pragma unroll
            for (int mt = 0; mt < 4; mt++) {
                const int rt = (wid >> 2) * 4 + mt;
                const uint4 pk = *(const uint4*)&Ac[(kk * 8 + rt) * 128 + lane * 4];
                af[mt][0] = pk.x; af[mt][1] = pk.y; af[mt][2] = pk.z; af[mt][3] = pk.w;
            }
#pragma unroll
            for (int nt = 0; nt < 4; nt++) {
                const int d8t = (wid & 3) * 4 + nt;
                const uint2 pk = *(const uint2*)&Bc[(kk * 16 + d8t) * 64 + lane * 2];
                bf[nt][0] = pk.x; bf[nt][1] = pk.y;
            }
#pragma unroll
            for (int mt = 0; mt < 4; mt++)
#pragma unroll
                for (int nt = 0; nt < 4; nt++)
                    mma8(acc[mt][nt], af[mt], bf[nt]);
        }

        if (km + 1 < KM) {
            CTX_STS_A(&As[nxt * 4096]);
            if (km + 2 < KM) CTX_LOAD_A((km + 2) * 32);
        }
        __syncthreads();
    }

#pragma unroll
    for (int mt = 0; mt < 4; mt++)
#pragma unroll
        for (int nt = 0; nt < 4; nt++) {
            const int n = n0 + wn + mt * 16 + g;
            const int d = d0 + wd + nt * 8 + tig * 2;
            float2 v0 = make_float2(acc[mt][nt][0] * rq0[mt], acc[mt][nt][1] * rq0[mt]);
            float2 v1 = make_float2(acc[mt][nt][2] * rq1[mt], acc[mt][nt][3] * rq1[mt]);
            *(float2*)&out[((size_t)b * N_ + n) * C_ + d]       = v0;
            *(float2*)&out[((size_t)b * N_ + n + 8) * C_ + d]   = v1;
        }
}

// ---------------------------------------------------------------------------
extern "C" void kernel_launch(void* const* d_in, const int* in_sizes, int n_in,
                              void* d_out, int out_size) {
    const float* q = (const float*)d_in[0];
    const float* k = (const float*)d_in[1];
    const float* v = (const float*)d_in[2];
    float* out = (float*)d_out;

    const int smem_kv  = (2 * 4096 + 2 * 32 * STA) * 4;   // ~67.6 KB
    const int smem_ctx = (4 * 4096) * 4;                  // 64 KB
    cudaFuncSetAttribute(kv_kernel,  cudaFuncAttributeMaxDynamicSharedMemorySize, smem_kv);
    cudaFuncSetAttribute(ctx_kernel, cudaFuncAttributeMaxDynamicSharedMemorySize, smem_ctx);

    // 1) reciprocal norms only
    rnorm_kernel<<<(B_ * N_ + B_ * M_) / 8, 256>>>(q, k);
    // 2) split-K partial kv = (k*rk)^T @ v, packing fused into producer
    kv_kernel<<<dim3(C_ / 128, C_ / 128, B_ * SPLITS), 256, smem_kv>>>(k, v);
    // 2b) reduce partials -> packed tf32 kv
    reduce_kernel<<<(B_ * C_ * C_ / 2) / 256, 256>>>();
    // 3) out = (q @ kv) * rq, packing fused into producer
    ctx_kernel<<<dim3(C_ / 128, N_ / 128, B_), 256, smem_ctx>>>(q, out);
}